// round 10
// baseline (speedup 1.0000x reference)
#include <cuda_runtime.h>
#include <cuda_bf16.h>
#include <cstdint>

// ----------------------------------------------------------------------------
// ROUND 10 = RESUBMIT of round 9 (round 9 died to a broker/container infra
// failure before compile). Round-3 passing kernel (verbatim) + k_probe.
// k_probe is a controlled experiment: it contains exactly the instruction set
// {ldmatrix.x4, ldmatrix.x2, mma.sync.bf16, shfl_xor} that every 512MiB-
// tripping round used and the passing round didn't. It runs at full-chip
// residency (2960 blocks) but does ~nothing and writes only to g_probe.
// The numerical pipeline below is byte-identical to the round-3 pass.
// ----------------------------------------------------------------------------

#define EPSV 1e-5f
constexpr int L  = 520;
constexpr int LP = 528;          // 1 left pad + 7 right pad (zeroed), 16B-aligned rows
constexpr int NS = 1024;         // samples (B*T)

__device__ __align__(16) __nv_bfloat16 g_h1[(size_t)NS * 128 * LP];   // ~138 MB
__device__ __align__(16) __nv_bfloat16 g_h2[(size_t)NS * 256 * LP];   // ~277 MB
__device__ float g_probe[256];   // probe scratch (never read)

// packed fp32x2 FMA: d = a*b + d, lanewise on 2 floats
__device__ __forceinline__ void dfma2(unsigned long long &d,
                                      unsigned long long a,
                                      unsigned long long b) {
    asm("fma.rn.f32x2 %0, %1, %2, %0;" : "+l"(d) : "l"(a), "l"(b));
}

// ---------------- probe-only asm macros ----------------
__device__ __forceinline__ uint32_t smem_u32_probe(const void* p) {
    uint32_t a;
    asm("{ .reg .u64 t; cvta.to.shared.u64 t, %1; cvt.u32.u64 %0, t; }" : "=r"(a) : "l"(p));
    return a;
}
#define P_LDSM4(R0, R1, R2, R3, A)                                            \
    asm volatile("ldmatrix.sync.aligned.m8n8.x4.shared.b16 {%0,%1,%2,%3}, [%4];" \
                 : "=r"(R0), "=r"(R1), "=r"(R2), "=r"(R3) : "r"(A))
#define P_LDSM2(R0, R1, A)                                                    \
    asm volatile("ldmatrix.sync.aligned.m8n8.x2.shared.b16 {%0,%1}, [%2];"    \
                 : "=r"(R0), "=r"(R1) : "r"(A))
#define P_MMA(D0, D1, D2, D3, A0, A1, A2, A3, B0, B1)                         \
    asm volatile("mma.sync.aligned.m16n8k16.row.col.f32.bf16.bf16.f32 "       \
                 "{%0,%1,%2,%3}, {%4,%5,%6,%7}, {%8,%9}, {%0,%1,%2,%3};"      \
                 : "+f"(D0), "+f"(D1), "+f"(D2), "+f"(D3)                     \
                 : "r"(A0), "r"(A1), "r"(A2), "r"(A3), "r"(B0), "r"(B1))

// ----------------------------------------------------------------------------
// Probe: exercises ldmatrix/mma/shfl at full residency; writes only g_probe.
// Deterministic; identical values from every block (block 0 does the store).
// ----------------------------------------------------------------------------
__global__ void k_probe()
{
    __shared__ __align__(16) __nv_bfloat16 sA[16 * 16];
    __shared__ __align__(16) __nv_bfloat16 sB[16 * 16];
    const int tid = threadIdx.x, lane = tid & 31;

    if (tid < 256) {
        sA[tid] = __float2bfloat16((float)(tid & 15) * 0.25f);
        sB[tid] = __float2bfloat16((float)(tid >> 4) * 0.125f);
    }
    __syncthreads();

    const uint32_t sa = smem_u32_probe(sA);
    const uint32_t sbb = smem_u32_probe(sB);
    const uint32_t aAddr = sa + (lane & 15) * 32 + ((lane >> 4) << 4);
    const uint32_t bAddr = sbb + (lane & 7) * 32 + ((lane & 8) ? 16 : 0);

    uint32_t a0, a1, a2, a3, b0, b1;
    P_LDSM4(a0, a1, a2, a3, aAddr);
    P_LDSM2(b0, b1, bAddr);
    float d0 = 0.f, d1 = 0.f, d2 = 0.f, d3 = 0.f;
    P_MMA(d0, d1, d2, d3, a0, a1, a2, a3, b0, b1);
    float s = d0 + __shfl_xor_sync(0xffffffffu, d0, 1);
    s += __shfl_xor_sync(0xffffffffu, d1, 2);

    if (blockIdx.x == 0 && tid < 32) {
        g_probe[tid * 4 + 0] = d0;
        g_probe[tid * 4 + 1] = d1;
        g_probe[tid * 4 + 2] = d2;
        g_probe[tid * 4 + 3] = d3 + s;
    }
}

// ----------------------------------------------------------------------------
// Kernel A: conv1 (Cin=1) + BN + ReLU -> g_h1 (bf16, padded rows)   [round 3]
// ----------------------------------------------------------------------------
__global__ void k_conv1(const float* __restrict__ x,  const float* __restrict__ w1,
                        const float* __restrict__ b1, const float* __restrict__ g1,
                        const float* __restrict__ be1, const float* __restrict__ m1,
                        const float* __restrict__ v1)
{
    __shared__ float xs[L + 2];          // +2 guard elems (never read with valid data)
    __shared__ __align__(16) __nv_bfloat16 hs[32 * LP];
    __shared__ float cw[128 * 3];
    __shared__ float ca[128], cb[128];

    const int tid = threadIdx.x;        // 256 threads
    const int n   = blockIdx.x;

    for (int i = tid; i < L; i += 256) xs[i] = x[(size_t)n * L + i];
    if (tid < 2) xs[L + tid] = 0.f;
    for (int i = tid; i < 128 * 3; i += 256) cw[i] = w1[i];
    if (tid < 128) {
        float a = g1[tid] * rsqrtf(v1[tid] + EPSV);
        ca[tid] = a;
        cb[tid] = (b1[tid] - m1[tid]) * a + be1[tid];
    }
    __syncthreads();

    for (int pass = 0; pass < 4; pass++) {
        const int cl  = tid >> 3;              // 0..31 local channel
        const int c   = pass * 32 + cl;        // global channel
        const int seg = tid & 7;               // 8 segs * 66 = 528 = LP
        const float w0 = cw[c * 3 + 0], wa = cw[c * 3 + 1], wb = cw[c * 3 + 2];
        const float a = ca[c], b = cb[c];
        for (int p = seg * 66; p < seg * 66 + 66; p++) {
            float v;
            if (p == 0 || p > L) {
                v = 0.f;                        // padded columns
            } else {
                int l = p - 1;
                float xm = (l > 0)     ? xs[l - 1] : 0.f;
                float xp = (l < L - 1) ? xs[l + 1] : 0.f;
                float y  = w0 * xm + wa * xs[l] + wb * xp;
                v = fmaxf(fmaf(y, a, b), 0.f);
            }
            hs[cl * LP + p] = __float2bfloat16(v);
        }
        __syncthreads();
        uint4*       dstv = reinterpret_cast<uint4*>(g_h1 + ((size_t)n * 128 + pass * 32) * LP);
        const uint4* srcv = reinterpret_cast<const uint4*>(hs);
        for (int i = tid; i < 32 * LP * 2 / 16; i += 256) dstv[i] = srcv[i];
        __syncthreads();
    }
}

// ----------------------------------------------------------------------------
// Kernel B: conv (CIN -> 256) + BN + ReLU as GEMM with 3 shifted taps [round 3]
// ----------------------------------------------------------------------------
template <int CIN, bool FUSE>
__global__ __launch_bounds__(256, 2)
void k_conv(const float* __restrict__ w,  const float* __restrict__ bb,
            const float* __restrict__ gg, const float* __restrict__ be,
            const float* __restrict__ mm, const float* __restrict__ vv,
            float* __restrict__ out)
{
    constexpr int CIN3 = CIN * 3;
    constexpr int KC   = 16;          // input channels per chunk
    constexpr int JC   = KC * 3;      // 48 K-indices per chunk
    constexpr int NT   = 104;         // N tile (520 = 5*104)
    constexpr int NWIN = NT + 2;      // B window incl. taps
    constexpr int BSTR = 108;         // padded B row stride (float2 units)
    constexpr int ASTR = 132;         // padded A row stride (floats, 16B-aligned pairs)

    __shared__ __align__(16) float  As[JC * ASTR];       // A tile: [j][c2]
    __shared__ __align__(16) float2 Bs[KC * BSTR];       // B tile, duplicated {v,v}
    __shared__ float s_alpha[128], s_beta[128], s_red[128];

    const int tid    = threadIdx.x;
    const int n      = blockIdx.x;
    const int c2base = blockIdx.y * 128;
    const int tm     = tid & 31;      // M group: local c2 = tm*4 + (0..3)
    const int tn     = tid >> 5;      // warp id = N group: local l = tn*13 + (0..12)

    const __nv_bfloat16* __restrict__ src = FUSE ? g_h2 : g_h1;
    __nv_bfloat16* dst = g_h2;

    if (tid < 128) {
        int c2g = c2base + tid;
        float a = gg[c2g] * rsqrtf(vv[c2g] + EPSV);
        s_alpha[tid] = a;
        s_beta[tid]  = (bb[c2g] - mm[c2g]) * a + be[c2g];
        if (FUSE) s_red[tid] = 0.f;
    }
    if (!FUSE) {
        // zero the pad columns of our 128 destination rows
        if (tid < 128) {
            __nv_bfloat16* row = dst + ((size_t)n * 256 + c2base + tid) * LP;
            __nv_bfloat16 z = __float2bfloat16(0.f);
            row[0] = z;
#pragma unroll
            for (int p = L + 1; p < LP; p++) row[p] = z;
        }
    }
    float msum[4];
    if (FUSE) { msum[0] = msum[1] = msum[2] = msum[3] = 0.f; }

    const unsigned long long* __restrict__ BsU  =
        reinterpret_cast<const unsigned long long*>(Bs);
    const ulonglong2* __restrict__ AsU2 =
        reinterpret_cast<const ulonglong2*>(As);

    for (int nt = 0; nt < 5; nt++) {
        const int l0 = nt * NT;
        unsigned long long acc[2][13];
#pragma unroll
        for (int mj = 0; mj < 2; mj++)
#pragma unroll
            for (int ni = 0; ni < 13; ni++) acc[mj][ni] = 0ull;

        for (int ch = 0; ch < CIN / KC; ch++) {
            __syncthreads();   // previous tile fully consumed
            // --- load A tile: As[j][c2] = w[(c2base+c2)*CIN3 + ch*JC + j] ---
            for (int i = tid; i < 128 * JC; i += 256) {
                int c2 = i / JC, j = i - c2 * JC;
                As[j * ASTR + c2] = w[(size_t)(c2base + c2) * CIN3 + ch * JC + j];
            }
            // --- load B tile (bf16 -> duplicated f32 pair) ---
            const __nv_bfloat16* sb = src + ((size_t)n * CIN + ch * KC) * LP + l0;
            for (int i = tid; i < KC * NWIN; i += 256) {
                int r = i / NWIN, col = i - r * NWIN;
                float v = __bfloat162float(sb[(size_t)r * LP + col]);
                Bs[r * BSTR + col] = make_float2(v, v);
            }
            __syncthreads();
            // --- compute ---
#pragma unroll 1
            for (int c1 = 0; c1 < KC; c1++) {
                unsigned long long rb[15];
#pragma unroll
                for (int wv = 0; wv < 15; wv++)
                    rb[wv] = BsU[c1 * BSTR + tn * 13 + wv];
#pragma unroll
                for (int t = 0; t < 3; t++) {
                    const int j = c1 * 3 + t;
                    ulonglong2 rav = AsU2[j * (ASTR / 4) + tm];   // row j at j*33
#pragma unroll
                    for (int ni = 0; ni < 13; ni++) {
                        dfma2(acc[0][ni], rav.x, rb[ni + t]);
                        dfma2(acc[1][ni], rav.y, rb[ni + t]);
                    }
                }
            }
        }

        // --- epilogue for this N tile ---
#pragma unroll
        for (int mj = 0; mj < 2; mj++) {
            const int c2l0 = tm * 4 + mj * 2;
            const float a0 = s_alpha[c2l0],     b0 = s_beta[c2l0];
            const float a1 = s_alpha[c2l0 + 1], b1 = s_beta[c2l0 + 1];
            if (!FUSE) {
                __nv_bfloat16* r0 = dst + ((size_t)n * 256 + c2base + c2l0) * LP
                                        + l0 + tn * 13 + 1;
                __nv_bfloat16* r1 = r0 + LP;
#pragma unroll
                for (int ni = 0; ni < 13; ni++) {
                    float lo = __uint_as_float((unsigned)(acc[mj][ni] & 0xffffffffu));
                    float hi = __uint_as_float((unsigned)(acc[mj][ni] >> 32));
                    r0[ni] = __float2bfloat16(fmaxf(fmaf(lo, a0, b0), 0.f));
                    r1[ni] = __float2bfloat16(fmaxf(fmaf(hi, a1, b1), 0.f));
                }
            } else {
                float s0 = 0.f, s1 = 0.f;
#pragma unroll
                for (int ni = 0; ni < 13; ni++) {
                    float lo = __uint_as_float((unsigned)(acc[mj][ni] & 0xffffffffu));
                    float hi = __uint_as_float((unsigned)(acc[mj][ni] >> 32));
                    s0 += fmaxf(fmaf(lo, a0, b0), 0.f);
                    s1 += fmaxf(fmaf(hi, a1, b1), 0.f);
                }
                msum[mj * 2 + 0] += s0;
                msum[mj * 2 + 1] += s1;
            }
        }
    }

    if (FUSE) {
        __syncthreads();
#pragma unroll
        for (int q = 0; q < 4; q++) atomicAdd(&s_red[tm * 4 + q], msum[q]);
        __syncthreads();
        if (tid < 128)
            out[(size_t)n * 256 + c2base + tid] = s_red[tid] * (1.f / 520.f);
    }
}

// ----------------------------------------------------------------------------
// launch
// ----------------------------------------------------------------------------
extern "C" void kernel_launch(void* const* d_in, const int* in_sizes, int n_in,
                              void* d_out, int out_size)
{
    (void)in_sizes; (void)n_in; (void)out_size;
    const float* x   = (const float*)d_in[0];
    const float* w1  = (const float*)d_in[1];
    const float* b1  = (const float*)d_in[2];
    const float* w2  = (const float*)d_in[3];
    const float* b2  = (const float*)d_in[4];
    const float* w3  = (const float*)d_in[5];
    const float* b3  = (const float*)d_in[6];
    const float* g1  = (const float*)d_in[7];
    const float* be1 = (const float*)d_in[8];
    const float* m1  = (const float*)d_in[9];
    const float* v1  = (const float*)d_in[10];
    const float* g2  = (const float*)d_in[11];
    const float* be2 = (const float*)d_in[12];
    const float* m2  = (const float*)d_in[13];
    const float* v2  = (const float*)d_in[14];
    const float* g3  = (const float*)d_in[15];
    const float* be3 = (const float*)d_in[16];
    const float* m3  = (const float*)d_in[17];
    const float* v3  = (const float*)d_in[18];
    float* out = (float*)d_out;

    k_probe<<<2960, 256>>>();          // controlled experiment, ~10us
    k_conv1<<<NS, 256>>>(x, w1, b1, g1, be1, m1, v1);
    k_conv<128, false><<<dim3(NS, 2), 256>>>(w2, b2, g2, be2, m2, v2, nullptr);
    k_conv<256, true ><<<dim3(NS, 2), 256>>>(w3, b3, g3, be3, m3, v3, out);
}

// round 14
// speedup vs baseline: 1.2213x; 1.2213x over previous
#include <cuda_runtime.h>
#include <cuda_bf16.h>
#include <cstdint>

// ----------------------------------------------------------------------------
// SpatialFeatureExtractor — FFMA f32x2 path (known-good R3 pipeline) with
// vectorized tile loads.
//   x: [1024,520] fp32 -> h1: [1024,128,520] -> h2: [1024,256,520] -> out
// R14: (1) k_prep_w pre-transposes weights into tile layout [chunk][j][256]
// so the A-tile load is 6x uint4/thread (was 24 scalar strided LDG);
// (2) B-tile load via uint4 bf16x8 + integer-shift bf16->f32, BSTR 108->112.
// Compute loop / accumulators / epilogue byte-identical to the passing kernel.
// mma.sync path abandoned: 6 builds all tripped a ~512MiB local-pool alloc
// (~740B/thread local even under a 128-reg budget) — toolchain pathology.
// ----------------------------------------------------------------------------

#define EPSV 1e-5f
constexpr int L  = 520;
constexpr int LP = 528;          // 1 left pad + 7 right pad (zeroed), 16B-aligned rows
constexpr int NS = 1024;         // samples (B*T)

__device__ __align__(16) __nv_bfloat16 g_h1[(size_t)NS * 128 * LP];   // ~138 MB
__device__ __align__(16) __nv_bfloat16 g_h2[(size_t)NS * 256 * LP];   // ~277 MB
__device__ __align__(16) float g_wT2[8 * 48 * 256];    // [chunk][j][c2] for CIN=128
__device__ __align__(16) float g_wT3[16 * 48 * 256];   // [chunk][j][c2] for CIN=256

// packed fp32x2 FMA: d = a*b + d, lanewise on 2 floats
__device__ __forceinline__ void dfma2(unsigned long long &d,
                                      unsigned long long a,
                                      unsigned long long b) {
    asm("fma.rn.f32x2 %0, %1, %2, %0;" : "+l"(d) : "l"(a), "l"(b));
}

// ----------------------------------------------------------------------------
// Prep: transpose weights into tile-ready layout.
//   g_wT[chunk][j][c2] = w[c2*CIN3 + chunk*48 + j]
// ----------------------------------------------------------------------------
__global__ void k_prep_w(const float* __restrict__ w2, const float* __restrict__ w3)
{
    int i = blockIdx.x * 256 + threadIdx.x;
    if (i < 8 * 48 * 256) {
        int chunk = i / (48 * 256), rem = i % (48 * 256);
        int j = rem >> 8, c2 = rem & 255;
        g_wT2[i] = w2[c2 * 384 + chunk * 48 + j];
    } else {
        int i2 = i - 8 * 48 * 256;            // < 16*48*256
        int chunk = i2 / (48 * 256), rem = i2 % (48 * 256);
        int j = rem >> 8, c2 = rem & 255;
        g_wT3[i2] = w3[c2 * 768 + chunk * 48 + j];
    }
}

// ----------------------------------------------------------------------------
// Kernel A: conv1 (Cin=1) + BN + ReLU -> g_h1 (bf16, padded rows)  [unchanged]
// ----------------------------------------------------------------------------
__global__ void k_conv1(const float* __restrict__ x,  const float* __restrict__ w1,
                        const float* __restrict__ b1, const float* __restrict__ g1,
                        const float* __restrict__ be1, const float* __restrict__ m1,
                        const float* __restrict__ v1)
{
    __shared__ float xs[L + 2];
    __shared__ __align__(16) __nv_bfloat16 hs[32 * LP];
    __shared__ float cw[128 * 3];
    __shared__ float ca[128], cb[128];

    const int tid = threadIdx.x;        // 256 threads
    const int n   = blockIdx.x;

    for (int i = tid; i < L; i += 256) xs[i] = x[(size_t)n * L + i];
    if (tid < 2) xs[L + tid] = 0.f;
    for (int i = tid; i < 128 * 3; i += 256) cw[i] = w1[i];
    if (tid < 128) {
        float a = g1[tid] * rsqrtf(v1[tid] + EPSV);
        ca[tid] = a;
        cb[tid] = (b1[tid] - m1[tid]) * a + be1[tid];
    }
    __syncthreads();

    for (int pass = 0; pass < 4; pass++) {
        const int cl  = tid >> 3;
        const int c   = pass * 32 + cl;
        const int seg = tid & 7;
        const float w0 = cw[c * 3 + 0], wa = cw[c * 3 + 1], wb = cw[c * 3 + 2];
        const float a = ca[c], b = cb[c];
        for (int p = seg * 66; p < seg * 66 + 66; p++) {
            float v;
            if (p == 0 || p > L) {
                v = 0.f;
            } else {
                int l = p - 1;
                float xm = (l > 0)     ? xs[l - 1] : 0.f;
                float xp = (l < L - 1) ? xs[l + 1] : 0.f;
                float y  = w0 * xm + wa * xs[l] + wb * xp;
                v = fmaxf(fmaf(y, a, b), 0.f);
            }
            hs[cl * LP + p] = __float2bfloat16(v);
        }
        __syncthreads();
        uint4*       dstv = reinterpret_cast<uint4*>(g_h1 + ((size_t)n * 128 + pass * 32) * LP);
        const uint4* srcv = reinterpret_cast<const uint4*>(hs);
        for (int i = tid; i < 32 * LP * 2 / 16; i += 256) dstv[i] = srcv[i];
        __syncthreads();
    }
}

// ----------------------------------------------------------------------------
// Kernel B: conv (CIN -> 256) + BN + ReLU as GEMM with 3 shifted taps.
// Compute loop identical to the passing kernel; tile loads vectorized.
// ----------------------------------------------------------------------------
template <int CIN, bool FUSE>
__global__ __launch_bounds__(256, 2)
void k_conv(const float* __restrict__ bb,
            const float* __restrict__ gg, const float* __restrict__ be,
            const float* __restrict__ mm, const float* __restrict__ vv,
            float* __restrict__ out)
{
    constexpr int KC   = 16;          // input channels per chunk
    constexpr int JC   = KC * 3;      // 48 K-indices per chunk
    constexpr int NT   = 104;         // N tile (520 = 5*104)
    constexpr int BSTR = 112;         // padded B row stride (float2 units)
    constexpr int ASTR = 132;         // padded A row stride (floats)

    __shared__ __align__(16) float  As[JC * ASTR];       // A tile: [j][c2]
    __shared__ __align__(16) float2 Bs[KC * BSTR];       // B tile, duplicated {v,v}
    __shared__ float s_alpha[128], s_beta[128], s_red[128];

    const int tid    = threadIdx.x;
    const int n      = blockIdx.x;
    const int c2base = blockIdx.y * 128;
    const int tm     = tid & 31;      // M group: local c2 = tm*4 + (0..3)
    const int tn     = tid >> 5;      // warp id = N group: local l = tn*13 + (0..12)

    const __nv_bfloat16* __restrict__ src = FUSE ? g_h2 : g_h1;
    const float* __restrict__ gwT = FUSE ? g_wT3 : g_wT2;
    __nv_bfloat16* dst = g_h2;

    if (tid < 128) {
        int c2g = c2base + tid;
        float a = gg[c2g] * rsqrtf(vv[c2g] + EPSV);
        s_alpha[tid] = a;
        s_beta[tid]  = (bb[c2g] - mm[c2g]) * a + be[c2g];
        if (FUSE) s_red[tid] = 0.f;
    }
    if (!FUSE) {
        if (tid < 128) {
            __nv_bfloat16* row = dst + ((size_t)n * 256 + c2base + tid) * LP;
            __nv_bfloat16 z = __float2bfloat16(0.f);
            row[0] = z;
#pragma unroll
            for (int p = L + 1; p < LP; p++) row[p] = z;
        }
    }
    float msum[4];
    if (FUSE) { msum[0] = msum[1] = msum[2] = msum[3] = 0.f; }

    const unsigned long long* __restrict__ BsU  =
        reinterpret_cast<const unsigned long long*>(Bs);
    const ulonglong2* __restrict__ AsU2 =
        reinterpret_cast<const ulonglong2*>(As);

    for (int nt = 0; nt < 5; nt++) {
        const int l0 = nt * NT;
        unsigned long long acc[2][13];
#pragma unroll
        for (int mj = 0; mj < 2; mj++)
#pragma unroll
            for (int ni = 0; ni < 13; ni++) acc[mj][ni] = 0ull;

        for (int ch = 0; ch < CIN / KC; ch++) {
            __syncthreads();   // previous tile fully consumed
            // --- A tile: vectorized copy from pre-transposed weights ---
            // As[j][c2l] <- gwT[(ch*48 + j)*256 + c2base + c2l], 128 floats/row
            {
                const float* aSrc = gwT + (size_t)(ch * 48) * 256 + c2base;
                for (int i = tid; i < 1536; i += 256) {
                    int j = i >> 5, u = i & 31;           // 32 uint4 per row
                    *reinterpret_cast<uint4*>(&As[j * ASTR + u * 4]) =
                        *reinterpret_cast<const uint4*>(aSrc + (size_t)j * 256 + u * 4);
                }
            }
            // --- B tile: vectorized bf16x8 load, duplicated {v,v} stores ---
            // rows r<16, 14 uint4 per row covering cols 0..111 (compute reads <=105)
            {
                const __nv_bfloat16* sb = src + ((size_t)n * CIN + ch * KC) * LP + l0;
                if (tid < 224) {
                    int r = tid / 14, u = tid % 14;
                    uint4 v = *reinterpret_cast<const uint4*>(sb + (size_t)r * LP + u * 8);
                    float2* brow = &Bs[r * BSTR + u * 8];
#define BPUT(WORD, E)                                                         \
                    do {                                                      \
                        float lo_ = __uint_as_float((WORD) << 16);            \
                        float hi_ = __uint_as_float((WORD) & 0xFFFF0000u);    \
                        *reinterpret_cast<float4*>(brow + (E)) =              \
                            make_float4(lo_, lo_, hi_, hi_);                  \
                    } while (0)
                    BPUT(v.x, 0); BPUT(v.y, 2); BPUT(v.z, 4); BPUT(v.w, 6);
#undef BPUT
                }
            }
            __syncthreads();
            // --- compute (identical to passing kernel) ---
#pragma unroll 1
            for (int c1 = 0; c1 < KC; c1++) {
                unsigned long long rb[15];
#pragma unroll
                for (int wv = 0; wv < 15; wv++)
                    rb[wv] = BsU[c1 * BSTR + tn * 13 + wv];
#pragma unroll
                for (int t = 0; t < 3; t++) {
                    const int j = c1 * 3 + t;
                    ulonglong2 rav = AsU2[j * (ASTR / 4) + tm];   // row j at j*33
#pragma unroll
                    for (int ni = 0; ni < 13; ni++) {
                        dfma2(acc[0][ni], rav.x, rb[ni + t]);
                        dfma2(acc[1][ni], rav.y, rb[ni + t]);
                    }
                }
            }
        }

        // --- epilogue for this N tile (unchanged) ---
#pragma unroll
        for (int mj = 0; mj < 2; mj++) {
            const int c2l0 = tm * 4 + mj * 2;
            const float a0 = s_alpha[c2l0],     b0 = s_beta[c2l0];
            const float a1 = s_alpha[c2l0 + 1], b1 = s_beta[c2l0 + 1];
            if (!FUSE) {
                __nv_bfloat16* r0 = dst + ((size_t)n * 256 + c2base + c2l0) * LP
                                        + l0 + tn * 13 + 1;
                __nv_bfloat16* r1 = r0 + LP;
#pragma unroll
                for (int ni = 0; ni < 13; ni++) {
                    float lo = __uint_as_float((unsigned)(acc[mj][ni] & 0xffffffffu));
                    float hi = __uint_as_float((unsigned)(acc[mj][ni] >> 32));
                    r0[ni] = __float2bfloat16(fmaxf(fmaf(lo, a0, b0), 0.f));
                    r1[ni] = __float2bfloat16(fmaxf(fmaf(hi, a1, b1), 0.f));
                }
            } else {
                float s0 = 0.f, s1 = 0.f;
#pragma unroll
                for (int ni = 0; ni < 13; ni++) {
                    float lo = __uint_as_float((unsigned)(acc[mj][ni] & 0xffffffffu));
                    float hi = __uint_as_float((unsigned)(acc[mj][ni] >> 32));
                    s0 += fmaxf(fmaf(lo, a0, b0), 0.f);
                    s1 += fmaxf(fmaf(hi, a1, b1), 0.f);
                }
                msum[mj * 2 + 0] += s0;
                msum[mj * 2 + 1] += s1;
            }
        }
    }

    if (FUSE) {
        __syncthreads();
#pragma unroll
        for (int q = 0; q < 4; q++) atomicAdd(&s_red[tm * 4 + q], msum[q]);
        __syncthreads();
        if (tid < 128)
            out[(size_t)n * 256 + c2base + tid] = s_red[tid] * (1.f / 520.f);
    }
}

// ----------------------------------------------------------------------------
// launch
// ----------------------------------------------------------------------------
extern "C" void kernel_launch(void* const* d_in, const int* in_sizes, int n_in,
                              void* d_out, int out_size)
{
    (void)in_sizes; (void)n_in; (void)out_size;
    const float* x   = (const float*)d_in[0];
    const float* w1  = (const float*)d_in[1];
    const float* b1  = (const float*)d_in[2];
    const float* w2  = (const float*)d_in[3];
    const float* b2  = (const float*)d_in[4];
    const float* w3  = (const float*)d_in[5];
    const float* b3  = (const float*)d_in[6];
    const float* g1  = (const float*)d_in[7];
    const float* be1 = (const float*)d_in[8];
    const float* m1  = (const float*)d_in[9];
    const float* v1  = (const float*)d_in[10];
    const float* g2  = (const float*)d_in[11];
    const float* be2 = (const float*)d_in[12];
    const float* m2  = (const float*)d_in[13];
    const float* v2  = (const float*)d_in[14];
    const float* g3  = (const float*)d_in[15];
    const float* be3 = (const float*)d_in[16];
    const float* m3  = (const float*)d_in[17];
    const float* v3  = (const float*)d_in[18];
    float* out = (float*)d_out;

    k_prep_w<<<(8 * 48 * 256 + 16 * 48 * 256) / 256, 256>>>(w2, w3);
    k_conv1<<<NS, 256>>>(x, w1, b1, g1, be1, m1, v1);
    k_conv<128, false><<<dim3(NS, 2), 256>>>(b2, g2, be2, m2, v2, nullptr);
    k_conv<256, true ><<<dim3(NS, 2), 256>>>(b3, g3, be3, m3, v3, out);
}

// round 15
// speedup vs baseline: 1.2609x; 1.0324x over previous
#include <cuda_runtime.h>
#include <cuda_bf16.h>
#include <cstdint>

// ----------------------------------------------------------------------------
// SpatialFeatureExtractor — FFMA f32x2 path, double-buffered tile pipeline.
//   x: [1024,520] fp32 -> h1 -> h2 -> out [1024,256] (mean over L)
// R15: 2-stage smem pipeline per chunk: A tile streamed via cp.async.cg
// (zero staging regs), B tile via 4-reg staging (LDG early, convert+STS after
// compute). Compute loop / accumulators / epilogue byte-identical to R14.
// Dynamic smem 80.9KB (2 stages), 2 CTAs/SM, launch_bounds(256,2).
// ----------------------------------------------------------------------------

#define EPSV 1e-5f
constexpr int L  = 520;
constexpr int LP = 528;
constexpr int NS = 1024;

__device__ __align__(16) __nv_bfloat16 g_h1[(size_t)NS * 128 * LP];   // ~138 MB
__device__ __align__(16) __nv_bfloat16 g_h2[(size_t)NS * 256 * LP];   // ~277 MB
__device__ __align__(16) float g_wT2[8 * 48 * 256];    // [chunk][j][c2] CIN=128
__device__ __align__(16) float g_wT3[16 * 48 * 256];   // [chunk][j][c2] CIN=256

__device__ __forceinline__ void dfma2(unsigned long long &d,
                                      unsigned long long a,
                                      unsigned long long b) {
    asm("fma.rn.f32x2 %0, %1, %2, %0;" : "+l"(d) : "l"(a), "l"(b));
}
__device__ __forceinline__ uint32_t smem_u32(const void* p) {
    uint32_t a;
    asm("{ .reg .u64 t; cvta.to.shared.u64 t, %1; cvt.u32.u64 %0, t; }" : "=r"(a) : "l"(p));
    return a;
}
#define CPA16(DST, SRC)                                                       \
    asm volatile("cp.async.cg.shared.global [%0], [%1], 16;" :: "r"(DST), "l"(SRC))
#define CP_COMMIT() asm volatile("cp.async.commit_group;" ::: "memory")
#define CP_WAIT0()  asm volatile("cp.async.wait_group 0;" ::: "memory")

// ----------------------------------------------------------------------------
// Prep: transpose weights into tile layout g_wT[chunk][j][c2]
// ----------------------------------------------------------------------------
__global__ void k_prep_w(const float* __restrict__ w2, const float* __restrict__ w3)
{
    int i = blockIdx.x * 256 + threadIdx.x;
    if (i < 8 * 48 * 256) {
        int chunk = i / (48 * 256), rem = i % (48 * 256);
        int j = rem >> 8, c2 = rem & 255;
        g_wT2[i] = w2[c2 * 384 + chunk * 48 + j];
    } else {
        int i2 = i - 8 * 48 * 256;
        int chunk = i2 / (48 * 256), rem = i2 % (48 * 256);
        int j = rem >> 8, c2 = rem & 255;
        g_wT3[i2] = w3[c2 * 768 + chunk * 48 + j];
    }
}

// ----------------------------------------------------------------------------
// Layer 1: conv1d(1->128)+BN+ReLU -> g_h1 (bf16, padded rows)   [unchanged]
// ----------------------------------------------------------------------------
__global__ void k_conv1(const float* __restrict__ x,  const float* __restrict__ w1,
                        const float* __restrict__ b1, const float* __restrict__ g1,
                        const float* __restrict__ be1, const float* __restrict__ m1,
                        const float* __restrict__ v1)
{
    __shared__ float xs[L + 2];
    __shared__ __align__(16) __nv_bfloat16 hs[32 * LP];
    __shared__ float cw[128 * 3];
    __shared__ float ca[128], cb[128];

    const int tid = threadIdx.x;
    const int n   = blockIdx.x;

    for (int i = tid; i < L; i += 256) xs[i] = x[(size_t)n * L + i];
    if (tid < 2) xs[L + tid] = 0.f;
    for (int i = tid; i < 128 * 3; i += 256) cw[i] = w1[i];
    if (tid < 128) {
        float a = g1[tid] * rsqrtf(v1[tid] + EPSV);
        ca[tid] = a;
        cb[tid] = (b1[tid] - m1[tid]) * a + be1[tid];
    }
    __syncthreads();

    for (int pass = 0; pass < 4; pass++) {
        const int cl  = tid >> 3;
        const int c   = pass * 32 + cl;
        const int seg = tid & 7;
        const float w0 = cw[c * 3 + 0], wa = cw[c * 3 + 1], wb = cw[c * 3 + 2];
        const float a = ca[c], b = cb[c];
        for (int p = seg * 66; p < seg * 66 + 66; p++) {
            float v;
            if (p == 0 || p > L) {
                v = 0.f;
            } else {
                int l = p - 1;
                float xm = (l > 0)     ? xs[l - 1] : 0.f;
                float xp = (l < L - 1) ? xs[l + 1] : 0.f;
                float y  = w0 * xm + wa * xs[l] + wb * xp;
                v = fmaxf(fmaf(y, a, b), 0.f);
            }
            hs[cl * LP + p] = __float2bfloat16(v);
        }
        __syncthreads();
        uint4*       dstv = reinterpret_cast<uint4*>(g_h1 + ((size_t)n * 128 + pass * 32) * LP);
        const uint4* srcv = reinterpret_cast<const uint4*>(hs);
        for (int i = tid; i < 32 * LP * 2 / 16; i += 256) dstv[i] = srcv[i];
        __syncthreads();
    }
}

// ----------------------------------------------------------------------------
// Kernel B: conv (CIN -> 256) + BN + ReLU as GEMM, double-buffered pipeline.
// Dynamic smem layout (bytes):
//   [0, 2*25344)   A stages: [st][48 j][132 floats]
//   [50688, +2*14336) B stages: [st][16 r][112 float2 dup]
//   [79360) alpha[128] | [79872) beta[128] | [80384) red[128]   total 80896
// ----------------------------------------------------------------------------
constexpr int AST_B   = 48 * 132 * 4;          // 25344
constexpr int OFF_B   = 2 * AST_B;             // 50688
constexpr int BST_B   = 16 * 112 * 8;          // 14336
constexpr int OFF_AL  = OFF_B + 2 * BST_B;     // 79360
constexpr int OFF_BE  = OFF_AL + 512;
constexpr int OFF_RED = OFF_BE + 512;
constexpr int SMEM_DYN = OFF_RED + 512;        // 80896

template <int CIN, bool FUSE>
__global__ __launch_bounds__(256, 2)
void k_conv(const float* __restrict__ bb,
            const float* __restrict__ gg, const float* __restrict__ be,
            const float* __restrict__ mm, const float* __restrict__ vv,
            float* __restrict__ out)
{
    constexpr int KC   = 16;
    constexpr int NCH  = CIN / KC;    // 8 or 16
    constexpr int NT   = 104;
    constexpr int BSTR = 112;         // float2 units
    constexpr int ASTR = 132;         // floats

    extern __shared__ __align__(16) char smem[];
    const uint32_t sb = smem_u32(smem);

    const int tid    = threadIdx.x;
    const int n      = blockIdx.x;
    const int c2base = blockIdx.y * 128;
    const int tm     = tid & 31;
    const int tn     = tid >> 5;

    const __nv_bfloat16* __restrict__ src = FUSE ? g_h2 : g_h1;
    const float* __restrict__ gwT = FUSE ? g_wT3 : g_wT2;
    __nv_bfloat16* dst = g_h2;

    float* s_alpha = reinterpret_cast<float*>(smem + OFF_AL);
    float* s_beta  = reinterpret_cast<float*>(smem + OFF_BE);
    float* s_red   = reinterpret_cast<float*>(smem + OFF_RED);

    if (tid < 128) {
        int c2g = c2base + tid;
        float a = gg[c2g] * rsqrtf(vv[c2g] + EPSV);
        s_alpha[tid] = a;
        s_beta[tid]  = (bb[c2g] - mm[c2g]) * a + be[c2g];
        if (FUSE) s_red[tid] = 0.f;
    }
    if (!FUSE) {
        if (tid < 128) {
            __nv_bfloat16* row = dst + ((size_t)n * 256 + c2base + tid) * LP;
            __nv_bfloat16 z = __float2bfloat16(0.f);
            row[0] = z;
#pragma unroll
            for (int p = L + 1; p < LP; p++) row[p] = z;
        }
    }
    float msum[4];
    if (FUSE) { msum[0] = msum[1] = msum[2] = msum[3] = 0.f; }

    // B-loader coordinates (224 threads)
    const int br = tid / 14, bu = tid % 14;
    const bool bOn = (tid < 224);

    // A cp.async issue for chunk ch into stage st
#define A_ISSUE(CH, ST)                                                       \
    do {                                                                      \
        const float* aSrc_ = gwT + (size_t)((CH) * 48) * 256 + c2base;        \
        for (int i_ = tid; i_ < 1536; i_ += 256) {                            \
            int j_ = i_ >> 5, u_ = i_ & 31;                                   \
            CPA16(sb + (ST) * AST_B + (uint32_t)(j_ * ASTR + u_ * 4) * 4,     \
                  aSrc_ + (size_t)j_ * 256 + u_ * 4);                         \
        }                                                                     \
        CP_COMMIT();                                                          \
    } while (0)

    // B convert+store (from 4 named regs) into stage st
#define B_STORE(ST)                                                           \
    do {                                                                      \
        if (bOn) {                                                            \
            float2* brow_ = reinterpret_cast<float2*>(smem + OFF_B + (ST) * BST_B) \
                            + br * BSTR + bu * 8;                             \
            float lo_, hi_;                                                   \
            lo_ = __uint_as_float(vbx << 16); hi_ = __uint_as_float(vbx & 0xFFFF0000u); \
            *reinterpret_cast<float4*>(brow_ + 0) = make_float4(lo_, lo_, hi_, hi_); \
            lo_ = __uint_as_float(vby << 16); hi_ = __uint_as_float(vby & 0xFFFF0000u); \
            *reinterpret_cast<float4*>(brow_ + 2) = make_float4(lo_, lo_, hi_, hi_); \
            lo_ = __uint_as_float(vbz << 16); hi_ = __uint_as_float(vbz & 0xFFFF0000u); \
            *reinterpret_cast<float4*>(brow_ + 4) = make_float4(lo_, lo_, hi_, hi_); \
            lo_ = __uint_as_float(vbw << 16); hi_ = __uint_as_float(vbw & 0xFFFF0000u); \
            *reinterpret_cast<float4*>(brow_ + 6) = make_float4(lo_, lo_, hi_, hi_); \
        }                                                                     \
    } while (0)

#define B_LOAD(CH)                                                            \
    do {                                                                      \
        if (bOn) {                                                            \
            const __nv_bfloat16* sbp_ = src + ((size_t)n * CIN + (CH) * KC) * LP + l0; \
            uint4 t_ = *reinterpret_cast<const uint4*>(sbp_ + (size_t)br * LP + bu * 8); \
            vbx = t_.x; vby = t_.y; vbz = t_.z; vbw = t_.w;                   \
        }                                                                     \
    } while (0)

    for (int nt = 0; nt < 5; nt++) {
        const int l0 = nt * NT;
        unsigned long long acc[2][13];
#pragma unroll
        for (int mj = 0; mj < 2; mj++)
#pragma unroll
            for (int ni = 0; ni < 13; ni++) acc[mj][ni] = 0ull;

        uint32_t vbx = 0, vby = 0, vbz = 0, vbw = 0;

        // prologue: stage chunk 0 into buffers 0
        A_ISSUE(0, 0);
        B_LOAD(0);
        B_STORE(0);
        CP_WAIT0();
        __syncthreads();

#pragma unroll 1
        for (int ch = 0; ch < NCH; ch++) {
            const int st = ch & 1;
            if (ch + 1 < NCH) {
                A_ISSUE(ch + 1, st ^ 1);
                B_LOAD(ch + 1);
            }
            // --- compute chunk ch from stage st ---
            const unsigned long long* __restrict__ BsU =
                reinterpret_cast<const unsigned long long*>(smem + OFF_B + st * BST_B);
            const ulonglong2* __restrict__ AsU2 =
                reinterpret_cast<const ulonglong2*>(smem + st * AST_B);
#pragma unroll 1
            for (int c1 = 0; c1 < KC; c1++) {
                unsigned long long rb[15];
#pragma unroll
                for (int wv = 0; wv < 15; wv++)
                    rb[wv] = BsU[c1 * BSTR + tn * 13 + wv];
#pragma unroll
                for (int t = 0; t < 3; t++) {
                    const int j = c1 * 3 + t;
                    ulonglong2 rav = AsU2[j * (ASTR / 4) + tm];
#pragma unroll
                    for (int ni = 0; ni < 13; ni++) {
                        dfma2(acc[0][ni], rav.x, rb[ni + t]);
                        dfma2(acc[1][ni], rav.y, rb[ni + t]);
                    }
                }
            }
            if (ch + 1 < NCH) {
                B_STORE(st ^ 1);
                CP_WAIT0();
            }
            __syncthreads();
        }

        // --- epilogue for this N tile (unchanged) ---
#pragma unroll
        for (int mj = 0; mj < 2; mj++) {
            const int c2l0 = tm * 4 + mj * 2;
            const float a0 = s_alpha[c2l0],     b0 = s_beta[c2l0];
            const float a1 = s_alpha[c2l0 + 1], b1 = s_beta[c2l0 + 1];
            if (!FUSE) {
                __nv_bfloat16* r0 = dst + ((size_t)n * 256 + c2base + c2l0) * LP
                                        + l0 + tn * 13 + 1;
                __nv_bfloat16* r1 = r0 + LP;
#pragma unroll
                for (int ni = 0; ni < 13; ni++) {
                    float lo = __uint_as_float((unsigned)(acc[mj][ni] & 0xffffffffu));
                    float hi = __uint_as_float((unsigned)(acc[mj][ni] >> 32));
                    r0[ni] = __float2bfloat16(fmaxf(fmaf(lo, a0, b0), 0.f));
                    r1[ni] = __float2bfloat16(fmaxf(fmaf(hi, a1, b1), 0.f));
                }
            } else {
                float s0 = 0.f, s1 = 0.f;
#pragma unroll
                for (int ni = 0; ni < 13; ni++) {
                    float lo = __uint_as_float((unsigned)(acc[mj][ni] & 0xffffffffu));
                    float hi = __uint_as_float((unsigned)(acc[mj][ni] >> 32));
                    s0 += fmaxf(fmaf(lo, a0, b0), 0.f);
                    s1 += fmaxf(fmaf(hi, a1, b1), 0.f);
                }
                msum[mj * 2 + 0] += s0;
                msum[mj * 2 + 1] += s1;
            }
        }
    }
#undef A_ISSUE
#undef B_STORE
#undef B_LOAD

    if (FUSE) {
        __syncthreads();
#pragma unroll
        for (int q = 0; q < 4; q++) atomicAdd(&s_red[tm * 4 + q], msum[q]);
        __syncthreads();
        if (tid < 128)
            out[(size_t)n * 256 + c2base + tid] = s_red[tid] * (1.f / 520.f);
    }
}

// ----------------------------------------------------------------------------
// launch
// ----------------------------------------------------------------------------
extern "C" void kernel_launch(void* const* d_in, const int* in_sizes, int n_in,
                              void* d_out, int out_size)
{
    (void)in_sizes; (void)n_in; (void)out_size;
    const float* x   = (const float*)d_in[0];
    const float* w1  = (const float*)d_in[1];
    const float* b1  = (const float*)d_in[2];
    const float* w2  = (const float*)d_in[3];
    const float* b2  = (const float*)d_in[4];
    const float* w3  = (const float*)d_in[5];
    const float* b3  = (const float*)d_in[6];
    const float* g1  = (const float*)d_in[7];
    const float* be1 = (const float*)d_in[8];
    const float* m1  = (const float*)d_in[9];
    const float* v1  = (const float*)d_in[10];
    const float* g2  = (const float*)d_in[11];
    const float* be2 = (const float*)d_in[12];
    const float* m2  = (const float*)d_in[13];
    const float* v2  = (const float*)d_in[14];
    const float* g3  = (const float*)d_in[15];
    const float* be3 = (const float*)d_in[16];
    const float* m3  = (const float*)d_in[17];
    const float* v3  = (const float*)d_in[18];
    float* out = (float*)d_out;

    cudaFuncSetAttribute(k_conv<128, false>,
                         cudaFuncAttributeMaxDynamicSharedMemorySize, SMEM_DYN);
    cudaFuncSetAttribute(k_conv<256, true>,
                         cudaFuncAttributeMaxDynamicSharedMemorySize, SMEM_DYN);

    k_prep_w<<<(8 * 48 * 256 + 16 * 48 * 256) / 256, 256>>>(w2, w3);
    k_conv1<<<NS, 256>>>(x, w1, b1, g1, be1, m1, v1);
    k_conv<128, false><<<dim3(NS, 2), 256, SMEM_DYN>>>(b2, g2, be2, m2, v2, nullptr);
    k_conv<256, true ><<<dim3(NS, 2), 256, SMEM_DYN>>>(b3, g3, be3, m3, v3, out);
}

// round 16
// speedup vs baseline: 1.3309x; 1.0555x over previous
#include <cuda_runtime.h>
#include <cuda_bf16.h>
#include <cstdint>

// ----------------------------------------------------------------------------
// SpatialFeatureExtractor — FFMA f32x2 path, double-buffered pipeline,
// dual-parity B tile (R16).
//   x: [1024,520] fp32 -> h1 -> h2 -> out [1024,256] (mean over L)
// R16: B stored twice per row (Beven[j]=B[j], Bodd[j]=B[j+1]) so every warp's
// 15-wide duplicated-f32 window loads as 8 aligned LDS.128 instead of 15
// LDS.64. Inner loop: 11 LDS + 78 FFMA2 per c1 (was 18 + 78). Everything
// else (A path, accumulators, epilogue) identical to R15 -> bit-identical out.
// ----------------------------------------------------------------------------

#define EPSV 1e-5f
constexpr int L  = 520;
constexpr int LP = 528;
constexpr int NS = 1024;

__device__ __align__(16) __nv_bfloat16 g_h1[(size_t)NS * 128 * LP];   // ~138 MB
__device__ __align__(16) __nv_bfloat16 g_h2[(size_t)NS * 256 * LP];   // ~277 MB
__device__ __align__(16) float g_wT2[8 * 48 * 256];    // [chunk][j][c2] CIN=128
__device__ __align__(16) float g_wT3[16 * 48 * 256];   // [chunk][j][c2] CIN=256

__device__ __forceinline__ void dfma2(unsigned long long &d,
                                      unsigned long long a,
                                      unsigned long long b) {
    asm("fma.rn.f32x2 %0, %1, %2, %0;" : "+l"(d) : "l"(a), "l"(b));
}
__device__ __forceinline__ uint32_t smem_u32(const void* p) {
    uint32_t a;
    asm("{ .reg .u64 t; cvta.to.shared.u64 t, %1; cvt.u32.u64 %0, t; }" : "=r"(a) : "l"(p));
    return a;
}
#define CPA16(DST, SRC)                                                       \
    asm volatile("cp.async.cg.shared.global [%0], [%1], 16;" :: "r"(DST), "l"(SRC))
#define CP_COMMIT() asm volatile("cp.async.commit_group;" ::: "memory")
#define CP_WAIT0()  asm volatile("cp.async.wait_group 0;" ::: "memory")

// ----------------------------------------------------------------------------
// Prep: transpose weights into tile layout g_wT[chunk][j][c2]
// ----------------------------------------------------------------------------
__global__ void k_prep_w(const float* __restrict__ w2, const float* __restrict__ w3)
{
    int i = blockIdx.x * 256 + threadIdx.x;
    if (i < 8 * 48 * 256) {
        int chunk = i / (48 * 256), rem = i % (48 * 256);
        int j = rem >> 8, c2 = rem & 255;
        g_wT2[i] = w2[c2 * 384 + chunk * 48 + j];
    } else {
        int i2 = i - 8 * 48 * 256;
        int chunk = i2 / (48 * 256), rem = i2 % (48 * 256);
        int j = rem >> 8, c2 = rem & 255;
        g_wT3[i2] = w3[c2 * 768 + chunk * 48 + j];
    }
}

// ----------------------------------------------------------------------------
// Layer 1: conv1d(1->128)+BN+ReLU -> g_h1 (bf16, padded rows)   [unchanged]
// ----------------------------------------------------------------------------
__global__ void k_conv1(const float* __restrict__ x,  const float* __restrict__ w1,
                        const float* __restrict__ b1, const float* __restrict__ g1,
                        const float* __restrict__ be1, const float* __restrict__ m1,
                        const float* __restrict__ v1)
{
    __shared__ float xs[L + 2];
    __shared__ __align__(16) __nv_bfloat16 hs[32 * LP];
    __shared__ float cw[128 * 3];
    __shared__ float ca[128], cb[128];

    const int tid = threadIdx.x;
    const int n   = blockIdx.x;

    for (int i = tid; i < L; i += 256) xs[i] = x[(size_t)n * L + i];
    if (tid < 2) xs[L + tid] = 0.f;
    for (int i = tid; i < 128 * 3; i += 256) cw[i] = w1[i];
    if (tid < 128) {
        float a = g1[tid] * rsqrtf(v1[tid] + EPSV);
        ca[tid] = a;
        cb[tid] = (b1[tid] - m1[tid]) * a + be1[tid];
    }
    __syncthreads();

    for (int pass = 0; pass < 4; pass++) {
        const int cl  = tid >> 3;
        const int c   = pass * 32 + cl;
        const int seg = tid & 7;
        const float w0 = cw[c * 3 + 0], wa = cw[c * 3 + 1], wb = cw[c * 3 + 2];
        const float a = ca[c], b = cb[c];
        for (int p = seg * 66; p < seg * 66 + 66; p++) {
            float v;
            if (p == 0 || p > L) {
                v = 0.f;
            } else {
                int l = p - 1;
                float xm = (l > 0)     ? xs[l - 1] : 0.f;
                float xp = (l < L - 1) ? xs[l + 1] : 0.f;
                float y  = w0 * xm + wa * xs[l] + wb * xp;
                v = fmaxf(fmaf(y, a, b), 0.f);
            }
            hs[cl * LP + p] = __float2bfloat16(v);
        }
        __syncthreads();
        uint4*       dstv = reinterpret_cast<uint4*>(g_h1 + ((size_t)n * 128 + pass * 32) * LP);
        const uint4* srcv = reinterpret_cast<const uint4*>(hs);
        for (int i = tid; i < 32 * LP * 2 / 16; i += 256) dstv[i] = srcv[i];
        __syncthreads();
    }
}

// ----------------------------------------------------------------------------
// Kernel B: GEMM-conv, double-buffered, dual-parity B tile.
// Dynamic smem (bytes):
//   [0, 2*25344)       A stages: [st][48 j][132 floats]
//   [50688, +2*28672)  B stages: [st][16 r][ Beven 112 f2 | Bodd 112 f2 ]
//   [108032) alpha | [108544) beta | [109056) red    total 109568
// ----------------------------------------------------------------------------
constexpr int AST_B   = 48 * 132 * 4;          // 25344
constexpr int OFF_B   = 2 * AST_B;             // 50688
constexpr int BROWB   = 224 * 8;               // 1792 B per c1 row
constexpr int BST_B   = 16 * BROWB;            // 28672
constexpr int OFF_AL  = OFF_B + 2 * BST_B;     // 108032
constexpr int OFF_BE  = OFF_AL + 512;
constexpr int OFF_RED = OFF_BE + 512;
constexpr int SMEM_DYN = OFF_RED + 512;        // 109568

template <int CIN, bool FUSE>
__global__ __launch_bounds__(256, 2)
void k_conv(const float* __restrict__ bb,
            const float* __restrict__ gg, const float* __restrict__ be,
            const float* __restrict__ mm, const float* __restrict__ vv,
            float* __restrict__ out)
{
    constexpr int KC   = 16;
    constexpr int NCH  = CIN / KC;    // 8 or 16
    constexpr int NT   = 104;
    constexpr int ASTR = 132;         // floats

    extern __shared__ __align__(16) char smem[];
    const uint32_t sb = smem_u32(smem);

    const int tid    = threadIdx.x;
    const int n      = blockIdx.x;
    const int c2base = blockIdx.y * 128;
    const int tm     = tid & 31;
    const int tn     = tid >> 5;

    const __nv_bfloat16* __restrict__ src = FUSE ? g_h2 : g_h1;
    const float* __restrict__ gwT = FUSE ? g_wT3 : g_wT2;
    __nv_bfloat16* dst = g_h2;

    float* s_alpha = reinterpret_cast<float*>(smem + OFF_AL);
    float* s_beta  = reinterpret_cast<float*>(smem + OFF_BE);
    float* s_red   = reinterpret_cast<float*>(smem + OFF_RED);

    if (tid < 128) {
        int c2g = c2base + tid;
        float a = gg[c2g] * rsqrtf(vv[c2g] + EPSV);
        s_alpha[tid] = a;
        s_beta[tid]  = (bb[c2g] - mm[c2g]) * a + be[c2g];
        if (FUSE) s_red[tid] = 0.f;
    }
    if (!FUSE) {
        if (tid < 128) {
            __nv_bfloat16* row = dst + ((size_t)n * 256 + c2base + tid) * LP;
            __nv_bfloat16 z = __float2bfloat16(0.f);
            row[0] = z;
#pragma unroll
            for (int p = L + 1; p < LP; p++) row[p] = z;
        }
    }
    float msum[4];
    if (FUSE) { msum[0] = msum[1] = msum[2] = msum[3] = 0.f; }

    // B-loader coordinates (224 threads): row br, 8 positions from p0
    const int br = tid / 14, bu = tid % 14, p0 = bu * 8;
    const bool bOn = (tid < 224);

    // per-warp B window byte offset inside a c1 row:
    //   even tn: Beven at float2 idx k ; odd tn: Bodd at float2 idx 112+(k-1)
    // both give loaded window w -> B[k+w], w = 0..15 (uses 0..14).
    const int kpos = tn * 13;
    const uint32_t bWin = (tn & 1) ? (uint32_t)(112 + kpos - 1) * 8
                                   : (uint32_t)kpos * 8;

#define A_ISSUE(CH, ST)                                                       \
    do {                                                                      \
        const float* aSrc_ = gwT + (size_t)((CH) * 48) * 256 + c2base;        \
        for (int i_ = tid; i_ < 1536; i_ += 256) {                            \
            int j_ = i_ >> 5, u_ = i_ & 31;                                   \
            CPA16(sb + (ST) * AST_B + (uint32_t)(j_ * ASTR + u_ * 4) * 4,     \
                  aSrc_ + (size_t)j_ * 256 + u_ * 4);                         \
        }                                                                     \
        CP_COMMIT();                                                          \
    } while (0)

#define B_LOAD(CH)                                                            \
    do {                                                                      \
        if (bOn) {                                                            \
            const __nv_bfloat16* sbp_ = src + ((size_t)n * CIN + (CH) * KC) * LP + l0; \
            uint4 t_ = *reinterpret_cast<const uint4*>(sbp_ + (size_t)br * LP + p0); \
            vbx = t_.x; vby = t_.y; vbz = t_.z; vbw = t_.w;                   \
        }                                                                     \
    } while (0)

    // store 8 values (v0..v7 from vbx..vbw) to Beven[p0..p0+7] and Bodd[p0-1..p0+6]
#define B_STORE(ST)                                                           \
    do {                                                                      \
        if (bOn) {                                                            \
            float2* row_ = reinterpret_cast<float2*>(smem + OFF_B + (ST) * BST_B \
                                                     + br * BROWB);           \
            float2* be_ = row_ + p0;                                          \
            float2* bo_ = row_ + 112 + p0 - 1;                                \
            float l0_, h0_, l1_, h1_, l2_, h2_, l3_, h3_;                     \
            l0_ = __uint_as_float(vbx << 16); h0_ = __uint_as_float(vbx & 0xFFFF0000u); \
            l1_ = __uint_as_float(vby << 16); h1_ = __uint_as_float(vby & 0xFFFF0000u); \
            l2_ = __uint_as_float(vbz << 16); h2_ = __uint_as_float(vbz & 0xFFFF0000u); \
            l3_ = __uint_as_float(vbw << 16); h3_ = __uint_as_float(vbw & 0xFFFF0000u); \
            *reinterpret_cast<float4*>(be_ + 0) = make_float4(l0_, l0_, h0_, h0_); \
            *reinterpret_cast<float4*>(be_ + 2) = make_float4(l1_, l1_, h1_, h1_); \
            *reinterpret_cast<float4*>(be_ + 4) = make_float4(l2_, l2_, h2_, h2_); \
            *reinterpret_cast<float4*>(be_ + 6) = make_float4(l3_, l3_, h3_, h3_); \
            if (p0 > 0) bo_[0] = make_float2(l0_, l0_);                       \
            bo_[1] = make_float2(h0_, h0_);                                   \
            bo_[2] = make_float2(l1_, l1_);                                   \
            bo_[3] = make_float2(h1_, h1_);                                   \
            bo_[4] = make_float2(l2_, l2_);                                   \
            bo_[5] = make_float2(h2_, h2_);                                   \
            bo_[6] = make_float2(l3_, l3_);                                   \
            bo_[7] = make_float2(h3_, h3_);                                   \
        }                                                                     \
    } while (0)

    for (int nt = 0; nt < 5; nt++) {
        const int l0 = nt * NT;
        unsigned long long acc[2][13];
#pragma unroll
        for (int mj = 0; mj < 2; mj++)
#pragma unroll
            for (int ni = 0; ni < 13; ni++) acc[mj][ni] = 0ull;

        uint32_t vbx = 0, vby = 0, vbz = 0, vbw = 0;

        A_ISSUE(0, 0);
        B_LOAD(0);
        B_STORE(0);
        CP_WAIT0();
        __syncthreads();

#pragma unroll 1
        for (int ch = 0; ch < NCH; ch++) {
            const int st = ch & 1;
            if (ch + 1 < NCH) {
                A_ISSUE(ch + 1, st ^ 1);
                B_LOAD(ch + 1);
            }
            const ulonglong2* __restrict__ AsU2 =
                reinterpret_cast<const ulonglong2*>(smem + st * AST_B);
            const char* __restrict__ bStage = smem + OFF_B + st * BST_B + bWin;
#pragma unroll 1
            for (int c1 = 0; c1 < KC; c1++) {
                ulonglong2 rbp[8];
                const ulonglong2* bp =
                    reinterpret_cast<const ulonglong2*>(bStage + c1 * BROWB);
#pragma unroll
                for (int i = 0; i < 8; i++) rbp[i] = bp[i];
#pragma unroll
                for (int t = 0; t < 3; t++) {
                    const int j = c1 * 3 + t;
                    ulonglong2 rav = AsU2[j * (ASTR / 4) + tm];
#pragma unroll
                    for (int ni = 0; ni < 13; ni++) {
                        const int wdx = ni + t;
                        unsigned long long bv = (wdx & 1) ? rbp[wdx >> 1].y
                                                          : rbp[wdx >> 1].x;
                        dfma2(acc[0][ni], rav.x, bv);
                        dfma2(acc[1][ni], rav.y, bv);
                    }
                }
            }
            if (ch + 1 < NCH) {
                B_STORE(st ^ 1);
                CP_WAIT0();
            }
            __syncthreads();
        }

        // --- epilogue for this N tile (unchanged) ---
#pragma unroll
        for (int mj = 0; mj < 2; mj++) {
            const int c2l0 = tm * 4 + mj * 2;
            const float a0 = s_alpha[c2l0],     b0 = s_beta[c2l0];
            const float a1 = s_alpha[c2l0 + 1], b1 = s_beta[c2l0 + 1];
            if (!FUSE) {
                __nv_bfloat16* r0 = dst + ((size_t)n * 256 + c2base + c2l0) * LP
                                        + l0 + tn * 13 + 1;
                __nv_bfloat16* r1 = r0 + LP;
#pragma unroll
                for (int ni = 0; ni < 13; ni++) {
                    float lo = __uint_as_float((unsigned)(acc[mj][ni] & 0xffffffffu));
                    float hi = __uint_as_float((unsigned)(acc[mj][ni] >> 32));
                    r0[ni] = __float2bfloat16(fmaxf(fmaf(lo, a0, b0), 0.f));
                    r1[ni] = __float2bfloat16(fmaxf(fmaf(hi, a1, b1), 0.f));
                }
            } else {
                float s0 = 0.f, s1 = 0.f;
#pragma unroll
                for (int ni = 0; ni < 13; ni++) {
                    float lo = __uint_as_float((unsigned)(acc[mj][ni] & 0xffffffffu));
                    float hi = __uint_as_float((unsigned)(acc[mj][ni] >> 32));
                    s0 += fmaxf(fmaf(lo, a0, b0), 0.f);
                    s1 += fmaxf(fmaf(hi, a1, b1), 0.f);
                }
                msum[mj * 2 + 0] += s0;
                msum[mj * 2 + 1] += s1;
            }
        }
    }
#undef A_ISSUE
#undef B_LOAD
#undef B_STORE

    if (FUSE) {
        __syncthreads();
#pragma unroll
        for (int q = 0; q < 4; q++) atomicAdd(&s_red[tm * 4 + q], msum[q]);
        __syncthreads();
        if (tid < 128)
            out[(size_t)n * 256 + c2base + tid] = s_red[tid] * (1.f / 520.f);
    }
}

// ----------------------------------------------------------------------------
// launch
// ----------------------------------------------------------------------------
extern "C" void kernel_launch(void* const* d_in, const int* in_sizes, int n_in,
                              void* d_out, int out_size)
{
    (void)in_sizes; (void)n_in; (void)out_size;
    const float* x   = (const float*)d_in[0];
    const float* w1  = (const float*)d_in[1];
    const float* b1  = (const float*)d_in[2];
    const float* w2  = (const float*)d_in[3];
    const float* b2  = (const float*)d_in[4];
    const float* w3  = (const float*)d_in[5];
    const float* b3  = (const float*)d_in[6];
    const float* g1  = (const float*)d_in[7];
    const float* be1 = (const float*)d_in[8];
    const float* m1  = (const float*)d_in[9];
    const float* v1  = (const float*)d_in[10];
    const float* g2  = (const float*)d_in[11];
    const float* be2 = (const float*)d_in[12];
    const float* m2  = (const float*)d_in[13];
    const float* v2  = (const float*)d_in[14];
    const float* g3  = (const float*)d_in[15];
    const float* be3 = (const float*)d_in[16];
    const float* m3  = (const float*)d_in[17];
    const float* v3  = (const float*)d_in[18];
    float* out = (float*)d_out;

    cudaFuncSetAttribute(k_conv<128, false>,
                         cudaFuncAttributeMaxDynamicSharedMemorySize, SMEM_DYN);
    cudaFuncSetAttribute(k_conv<256, true>,
                         cudaFuncAttributeMaxDynamicSharedMemorySize, SMEM_DYN);

    k_prep_w<<<(8 * 48 * 256 + 16 * 48 * 256) / 256, 256>>>(w2, w3);
    k_conv1<<<NS, 256>>>(x, w1, b1, g1, be1, m1, v1);
    k_conv<128, false><<<dim3(NS, 2), 256, SMEM_DYN>>>(b2, g2, be2, m2, v2, nullptr);
    k_conv<256, true ><<<dim3(NS, 2), 256, SMEM_DYN>>>(b3, g3, be3, m3, v3, out);
}